// round 16
// baseline (speedup 1.0000x reference)
#include <cuda_runtime.h>
#include <cuda_bf16.h>
#include <math.h>
#include <stdint.h>

#define T_ 4096
#define B_ 2
#define E_ 1024
#define H_ 16
#define D_ 64
#define W_ 256
#define G_ 64
#define M_ (B_*T_)   /* 8192 */
#define NSPLIT 8

typedef __nv_bfloat16 bf16;

// ---------------- scratch (device globals; no allocation) ----------------
__device__ bf16 g_xh[M_*E_];   // converted query (transposed to [B*T,E])
__device__ bf16 g_xl[M_*E_];
__device__ bf16 g_qh[M_*E_],  g_ql[M_*E_];
__device__ bf16 g_kh[M_*E_],  g_kl[M_*E_];
__device__ bf16 g_vh[M_*E_],  g_vl[M_*E_];
__device__ bf16 g_ah[M_*E_],  g_al[M_*E_];        // attention output (split)
__device__ bf16 g_wh[7*E_*E_], g_wl[7*E_*E_];      // Wq,Wk,Wv,Wkg,Wvg,Wo,Wqg
__device__ float g_kg[M_*E_];
__device__ float g_vg[M_*E_];
__device__ float g_qg[B_*G_*E_];
__device__ float g_part[(long)B_*H_*NSPLIT*G_*(D_+2)];

// ------------------------------ helpers ----------------------------------
__device__ __forceinline__ uint32_t smem_to_u32(const void* p) {
    uint32_t a;
    asm("{ .reg .u64 t; cvta.to.shared.u64 t, %1; cvt.u32.u64 %0, t; }"
        : "=r"(a) : "l"(p));
    return a;
}
#define SMEM_SWIZZLE_128B(o) ((o) ^ (((o) >> 3) & 0x70))
#define SMEM_SWIZZLE_64B(o)  ((o) ^ (((o) >> 3) & 0x30))

#define CP_ASYNC16(dst, src) \
    asm volatile("cp.async.cg.shared.global [%0], [%1], 16;" :: "r"(dst), "l"(src))
#define CP_COMMIT() asm volatile("cp.async.commit_group;" ::: "memory")
#define CP_WAIT1()  asm volatile("cp.async.wait_group 1;" ::: "memory")
#define CP_WAIT0()  asm volatile("cp.async.wait_group 0;" ::: "memory")

__device__ __forceinline__ void ldmx4(uint32_t* r, uint32_t addr) {
    asm volatile("ldmatrix.sync.aligned.m8n8.x4.shared.b16 {%0,%1,%2,%3}, [%4];"
        : "=r"(r[0]), "=r"(r[1]), "=r"(r[2]), "=r"(r[3]) : "r"(addr));
}
__device__ __forceinline__ void ldmx4t(uint32_t* r, uint32_t addr) {
    asm volatile("ldmatrix.sync.aligned.m8n8.x4.trans.shared.b16 {%0,%1,%2,%3}, [%4];"
        : "=r"(r[0]), "=r"(r[1]), "=r"(r[2]), "=r"(r[3]) : "r"(addr));
}
__device__ __forceinline__ void mma16816(float* d, const uint32_t* a, const uint32_t* b) {
    asm volatile("mma.sync.aligned.m16n8k16.row.col.f32.bf16.bf16.f32 "
        "{%0,%1,%2,%3}, {%4,%5,%6,%7}, {%8,%9}, {%0,%1,%2,%3};"
        : "+f"(d[0]), "+f"(d[1]), "+f"(d[2]), "+f"(d[3])
        : "r"(a[0]), "r"(a[1]), "r"(a[2]), "r"(a[3]), "r"(b[0]), "r"(b[1]));
}

__device__ __forceinline__ void split4(float4 v, uint2& hi, uint2& lo) {
    __nv_bfloat162 h0 = __float22bfloat162_rn(make_float2(v.x, v.y));
    __nv_bfloat162 h1 = __float22bfloat162_rn(make_float2(v.z, v.w));
    float2 f0 = __bfloat1622float2(h0);
    float2 f1 = __bfloat1622float2(h1);
    __nv_bfloat162 l0 = __float22bfloat162_rn(make_float2(v.x - f0.x, v.y - f0.y));
    __nv_bfloat162 l1 = __float22bfloat162_rn(make_float2(v.z - f1.x, v.w - f1.y));
    hi.x = *(uint32_t*)&h0; hi.y = *(uint32_t*)&h1;
    lo.x = *(uint32_t*)&l0; lo.y = *(uint32_t*)&l1;
}
__device__ __forceinline__ void splitpack(float a, float b, uint32_t& hi, uint32_t& lo) {
    __nv_bfloat162 h = __float22bfloat162_rn(make_float2(a, b));
    float2 f = __bfloat1622float2(h);
    __nv_bfloat162 l2 = __float22bfloat162_rn(make_float2(a - f.x, b - f.y));
    hi = *(uint32_t*)&h; lo = *(uint32_t*)&l2;
}

// -------------------- one-time split conversions (4x ILP) -----------------
struct ConvBatch {
    const float* src[7];
    bf16* oh[7];
    bf16* ol[7];
};
__global__ __launch_bounds__(256) void conv_batch_kernel(ConvBatch cb)
{
    int z = blockIdx.y;
    const float4* src = (const float4*)cb.src[z];
    uint2* oh = (uint2*)cb.oh[z];
    uint2* ol = (uint2*)cb.ol[z];
    int base = blockIdx.x*1024 + threadIdx.x;
    float4 v[4];
    #pragma unroll
    for (int u = 0; u < 4; u++) v[u] = src[base + u*256];
    #pragma unroll
    for (int u = 0; u < 4; u++) {
        uint2 h, l; split4(v[u], h, l);
        oh[base + u*256] = h; ol[base + u*256] = l;
    }
}
// query [T,B,E] fp32 -> [B*T,E] split bf16
__global__ __launch_bounds__(256) void conv_query_kernel(
    const float* __restrict__ q, bf16* __restrict__ oh, bf16* __restrict__ ol)
{
    int base = blockIdx.x*1024 + threadIdx.x;
    float4 v[4];
    #pragma unroll
    for (int u = 0; u < 4; u++) {
        int i = base + u*256;
        int m = i >> 8, c = i & 255;
        int b = m >> 12, t = m & 4095;
        v[u] = ((const float4*)q)[(t*B_ + b)*256 + c];
    }
    #pragma unroll
    for (int u = 0; u < 4; u++) {
        int i = base + u*256;
        uint2 h, l; split4(v[u], h, l);
        ((uint2*)oh)[i] = h; ((uint2*)ol)[i] = l;
    }
}

// === batched GEMM v4 (1114us champion — FROZEN) ==========================
#define G4_STAGE 32768
#define G4_SMEM  (3*G4_STAGE + 1024)
#define G3_NB 5

struct G3Batch {
    const bf16* Ah[G3_NB]; const bf16* Al[G3_NB];
    const bf16* Bh[G3_NB]; const bf16* Bl[G3_NB];
    const float* bias[G3_NB];
    float alpha[G3_NB];
    float* Cf[G3_NB];
    bf16* Ch[G3_NB]; bf16* Cl[G3_NB];
    int omode[G3_NB];
};

__global__ __launch_bounds__(256, 2) void gemm4_kernel(G3Batch bt)
{
    extern __shared__ char dsm_raw[];
    char* dsm = (char*)(((uintptr_t)dsm_raw + 1023) & ~(uintptr_t)1023);
    const uint32_t sb = smem_to_u32(dsm);

    const int z = blockIdx.z;
    const int tid = threadIdx.x;
    const int wid = tid >> 5;
    const int lid = tid & 31;
    const int m0  = blockIdx.y * 128;
    const int n0  = blockIdx.x * 128;
    const int wm  = wid & 3;
    const int wn  = wid >> 2;

    const bf16* gptr[8];
    uint32_t dst_rel[8];
    {
        const bf16* Abase[2] = { bt.Ah[z], bt.Al[z] };
        const bf16* Bbase[2] = { bt.Bh[z], bt.Bl[z] };
        #pragma unroll
        for (int j = 0; j < 8; j++) {
            int idx = tid + j*256;
            int mat = idx >> 9;
            int e   = idx & 511;
            int r   = e >> 2, ch = e & 3;
            long row = (mat < 2) ? (long)(m0 + r) : (long)(n0 + r);
            const bf16* base = (mat < 2) ? Abase[mat] : Bbase[mat - 2];
            gptr[j] = base + row*E_ + ch*8;
            dst_rel[j] = (uint32_t)(mat*8192) + SMEM_SWIZZLE_64B((uint32_t)(r*64 + ch*16));
        }
    }

    const int laA = lid & 15;
    const uint32_t koChA = (uint32_t)((lid >> 4) * 16);
    const uint32_t xorA  = (uint32_t)(((laA >> 1) & 3) * 16);
    const uint32_t rowA0 = (uint32_t)((wm*32 + laA) * 64);
    const int laB = (lid & 7) + ((lid >> 4) & 1) * 8;
    const uint32_t koChB = (uint32_t)(((lid >> 3) & 1) * 16);
    const uint32_t xorB  = (uint32_t)(((laB >> 1) & 3) * 16);
    const uint32_t rowB0 = (uint32_t)((wn*64 + laB) * 64);

    float acc[2][8][4];
    #pragma unroll
    for (int mt = 0; mt < 2; mt++)
        #pragma unroll
        for (int nt = 0; nt < 8; nt++)
            #pragma unroll
            for (int e = 0; e < 4; e++) acc[mt][nt][e] = 0.f;

    #pragma unroll
    for (int p = 0; p < 2; p++) {
        const uint32_t base = sb + (uint32_t)p * G4_STAGE;
        #pragma unroll
        for (int j = 0; j < 8; j++) {
            CP_ASYNC16(base + dst_rel[j], gptr[j]);
            gptr[j] += 32;
        }
        CP_COMMIT();
    }

    int stage = 0;
    #pragma unroll 1
    for (int c = 0; c < 32; c++) {
        CP_WAIT1();
        __syncthreads();
        if (c + 2 < 32) {
            int s2 = stage + 2; if (s2 >= 3) s2 -= 3;
            const uint32_t base = sb + (uint32_t)s2 * G4_STAGE;
            #pragma unroll
            for (int j = 0; j < 8; j++) {
                CP_ASYNC16(base + dst_rel[j], gptr[j]);
                gptr[j] += 32;
            }
        }
        CP_COMMIT();

        const uint32_t st = sb + (uint32_t)stage * G4_STAGE;
        #pragma unroll
        for (int k16 = 0; k16 < 2; k16++) {
            const uint32_t koA = (uint32_t)(k16*32) + koChA;
            const uint32_t koB = (uint32_t)(k16*32) + koChB;
            uint32_t bh[4][4];
            #pragma unroll
            for (int g = 0; g < 4; g++)
                ldmx4(bh[g], st + 16384 + rowB0 + (uint32_t)(g*1024) + (koB ^ xorB));
            uint32_t ah[2][4];
            #pragma unroll
            for (int mt = 0; mt < 2; mt++)
                ldmx4(ah[mt], st + rowA0 + (uint32_t)(mt*1024) + (koA ^ xorA));
            #pragma unroll
            for (int mt = 0; mt < 2; mt++)
                #pragma unroll
                for (int nt = 0; nt < 8; nt++)
                    mma16816(acc[mt][nt], ah[mt], &bh[nt >> 1][(nt & 1)*2]);
            uint32_t al[2][4];
            #pragma unroll
            for (int mt = 0; mt < 2; mt++)
                ldmx4(al[mt], st + 8192 + rowA0 + (uint32_t)(mt*1024) + (koA ^ xorA));
            #pragma unroll
            for (int mt = 0; mt < 2; mt++)
                #pragma unroll
                for (int nt = 0; nt < 8; nt++)
                    mma16816(acc[mt][nt], al[mt], &bh[nt >> 1][(nt & 1)*2]);
            uint32_t bl[4][4];
            #pragma unroll
            for (int g = 0; g < 4; g++)
                ldmx4(bl[g], st + 24576 + rowB0 + (uint32_t)(g*1024) + (koB ^ xorB));
            #pragma unroll
            for (int mt = 0; mt < 2; mt++)
                #pragma unroll
                for (int nt = 0; nt < 8; nt++)
                    mma16816(acc[mt][nt], ah[mt], &bl[nt >> 1][(nt & 1)*2]);
        }
        stage++; if (stage >= 3) stage -= 3;
    }

    const int omode = bt.omode[z];
    const float alpha = bt.alpha[z];
    const float* __restrict__ bias = bt.bias[z];
    const int qrow = lid >> 2;
    const int qcol = (lid & 3) * 2;
    #pragma unroll
    for (int mt = 0; mt < 2; mt++) {
        #pragma unroll
        for (int half = 0; half < 2; half++) {
            long m = m0 + wm*32 + mt*16 + qrow + half*8;
            long obase;
            if (omode == 1) { long b = m >> 12, t = m & 4095; obase = (t*B_ + b)*(long)E_; }
            else            { obase = m * (long)E_; }
            #pragma unroll
            for (int nt = 0; nt < 8; nt++) {
                int col = n0 + wn*64 + nt*8 + qcol;
                float2 bi = *(const float2*)&bias[col];
                float v0 = (acc[mt][nt][half*2+0] + bi.x) * alpha;
                float v1 = (acc[mt][nt][half*2+1] + bi.y) * alpha;
                if (omode == 2) {
                    uint32_t hi, lo; splitpack(v0, v1, hi, lo);
                    *(uint32_t*)(bt.Ch[z] + obase + col) = hi;
                    *(uint32_t*)(bt.Cl[z] + obase + col) = lo;
                } else {
                    *(float2*)(bt.Cf[z] + obase + col) = make_float2(v0, v1);
                }
            }
        }
    }
}

// ======= qg projection v2 (FROZEN): pre-split inputs, split-K ============
#define G3_STAGE 65536
#define QG_SMEM (2*G3_STAGE + 1024)

__global__ __launch_bounds__(256, 1) void qg2_kernel(
    const bf16* __restrict__ Ah, const bf16* __restrict__ Al,
    const bf16* __restrict__ Bh, const bf16* __restrict__ Bl,
    const float* __restrict__ bias, float* __restrict__ C, float alpha)
{
    extern __shared__ char dsm_raw[];
    char* dsm = (char*)(((uintptr_t)dsm_raw + 1023) & ~(uintptr_t)1023);
    const uint32_t sb = smem_to_u32(dsm);

    const int tid = threadIdx.x;
    const int wid = tid >> 5;
    const int lid = tid & 31;
    const int n0  = blockIdx.x * 128;
    const int ks  = blockIdx.y;          // k slice 0..7 (128 K each)
    const int wm  = wid & 3;
    const int wn  = wid >> 2;

    uint32_t dsw[4]; long aoff[4], boff[4];
    #pragma unroll
    for (int j = 0; j < 4; j++) {
        int idx = tid + j*256;
        int r = idx >> 3, ch = idx & 7;
        dsw[j]  = SMEM_SWIZZLE_128B((uint32_t)(r*128 + ch*16));
        long b = r >> 6, t = r & 63;
        aoff[j] = (b*T_ + t)*(long)E_ + ks*128 + ch*8;
        boff[j] = (long)(n0 + r)*E_ + ks*128 + ch*8;
    }

    const int laA = lid & 15;
    const uint32_t koChA = (uint32_t)((lid >> 4) * 16);
    uint32_t rowA[2], xorA[2];
    #pragma unroll
    for (int mt = 0; mt < 2; mt++) {
        int r = wm*32 + mt*16 + laA;
        rowA[mt] = (uint32_t)(r * 128);
        xorA[mt] = (uint32_t)((r & 7) * 16);
    }
    const int laB = (lid & 7) + ((lid >> 4) & 1) * 8;
    const uint32_t koChB = (uint32_t)(((lid >> 3) & 1) * 16);
    uint32_t rowB[4], xorB[4];
    #pragma unroll
    for (int g = 0; g < 4; g++) {
        int r = wn*64 + g*16 + laB;
        rowB[g] = (uint32_t)(r * 128);
        xorB[g] = (uint32_t)((r & 7) * 16);
    }

    float acc[2][8][4];
    #pragma unroll
    for (int mt = 0; mt < 2; mt++)
        #pragma unroll
        for (int nt = 0; nt < 8; nt++)
            #pragma unroll
            for (int e = 0; e < 4; e++) acc[mt][nt][e] = 0.f;

    #pragma unroll
    for (int p = 0; p < 2; p++) {
        const uint32_t base = sb + (uint32_t)p * G3_STAGE;
        const long k0 = (long)p * 64;
        #pragma unroll
        for (int j = 0; j < 4; j++) CP_ASYNC16(base + dsw[j],         Ah + aoff[j] + k0);
        #pragma unroll
        for (int j = 0; j < 4; j++) CP_ASYNC16(base + 16384 + dsw[j], Al + aoff[j] + k0);
        #pragma unroll
        for (int j = 0; j < 4; j++) CP_ASYNC16(base + 32768 + dsw[j], Bh + boff[j] + k0);
        #pragma unroll
        for (int j = 0; j < 4; j++) CP_ASYNC16(base + 49152 + dsw[j], Bl + boff[j] + k0);
        CP_COMMIT();
    }
    CP_WAIT0();
    __syncthreads();

    #pragma unroll
    for (int c = 0; c < 2; c++) {
        const uint32_t bAh = sb + (uint32_t)c * G3_STAGE;
        const uint32_t bAl = bAh + 16384;
        const uint32_t bBh = bAh + 32768;
        const uint32_t bBl = bAh + 49152;
        #pragma unroll
        for (int k16 = 0; k16 < 4; k16++) {
            const uint32_t koA = (uint32_t)(k16*32) + koChA;
            const uint32_t koB = (uint32_t)(k16*32) + koChB;
            uint32_t ah[2][4], al[2][4];
            #pragma unroll
            for (int mt = 0; mt < 2; mt++) {
                uint32_t off = rowA[mt] + (koA ^ xorA[mt]);
                ldmx4(ah[mt], bAh + off);
                ldmx4(al[mt], bAl + off);
            }
            uint32_t bh[4][4], bl[4][4];
            #pragma unroll
            for (int g = 0; g < 4; g++) {
                uint32_t off = rowB[g] + (koB ^ xorB[g]);
                ldmx4(bh[g], bBh + off);
                ldmx4(bl[g], bBl + off);
            }
            #pragma unroll
            for (int mt = 0; mt < 2; mt++)
                #pragma unroll
                for (int nt = 0; nt < 8; nt++) {
                    const int g = nt >> 1, hf = (nt & 1) * 2;
                    mma16816(acc[mt][nt], ah[mt], &bh[g][hf]);
                    mma16816(acc[mt][nt], ah[mt], &bl[g][hf]);
                    mma16816(acc[mt][nt], al[mt], &bh[g][hf]);
                }
        }
    }

    const int qrow = lid >> 2;
    const int qcol = (lid & 3) * 2;
    #pragma unroll
    for (int mt = 0; mt < 2; mt++)
        #pragma unroll
        for (int half = 0; half < 2; half++) {
            long m = wm*32 + mt*16 + qrow + half*8;
            #pragma unroll
            for (int nt = 0; nt < 8; nt++) {
                int col = n0 + wn*64 + nt*8 + qcol;
                float v0 = acc[mt][nt][half*2+0];
                float v1 = acc[mt][nt][half*2+1];
                if (ks == 0) { v0 += bias[col]; v1 += bias[col+1]; }
                atomicAdd(&C[m*E_ + col],     v0 * alpha);
                atomicAdd(&C[m*E_ + col + 1], v1 * alpha);
            }
        }
}

// ======== band + global-key attention v3: exp-zero mask elimination ======
#define BA2_SMEM (32768 + 3*32768 + 1024)

__global__ __launch_bounds__(256, 1) void band2_kernel(
    const bf16* __restrict__ qh, const bf16* __restrict__ ql,
    const bf16* __restrict__ kh, const bf16* __restrict__ kl,
    const bf16* __restrict__ vh, const bf16* __restrict__ vl,
    bf16* __restrict__ ah_out, bf16* __restrict__ al_out)
{
    extern __shared__ char dsm_raw[];
    char* dsm = (char*)(((uintptr_t)dsm_raw + 1023) & ~(uintptr_t)1023);
    const uint32_t sb = smem_to_u32(dsm);
    const int tid = threadIdx.x, wid = tid >> 5, lid = tid & 31;
    const int qt = blockIdx.x, hh = blockIdx.y, b = blockIdx.z;
    const int t0 = qt * 128;

    const bf16* qsrc[8]; uint32_t qdst[8];
    #pragma unroll
    for (int j = 0; j < 8; j++) {
        int idx = tid + j*256;
        int mq = idx >> 10, r = (idx >> 3) & 127, ch = idx & 7;
        qsrc[j] = (mq ? ql : qh) + ((long)(b*T_ + t0 + r))*E_ + hh*64 + ch*8;
        qdst[j] = sb + (uint32_t)(mq*16384) + SMEM_SWIZZLE_128B((uint32_t)(r*128 + ch*16));
    }
    const bf16* kvbase[8]; long kvrow[8]; uint32_t kvdst[8];
    #pragma unroll
    for (int j = 0; j < 8; j++) {
        int idx = tid + j*256;
        int mat = idx >> 9, r = (idx >> 3) & 63, ch = idx & 7;
        const bf16* p = (mat < 2) ? (mat == 0 ? kh : kl) : (mat == 2 ? vh : vl);
        kvbase[j] = p + ((long)(b*T_))*E_ + hh*64 + ch*8;
        kvrow[j]  = (long)r * E_;
        kvdst[j]  = (uint32_t)(mat*8192) + SMEM_SWIZZLE_128B((uint32_t)(r*128 + ch*16));
    }

    const int lo_t = (qt*2-4 > 0) ? qt*2-4 : 0;
    int hi_t = qt*2 + 5; if (hi_t > 63) hi_t = 63;
    const int extra = (lo_t > 0) ? 1 : 0;
    const int nblocks = hi_t - lo_t + 1 + extra;

    auto kb_of = [&](int i) { return extra ? ((i == 0) ? 0 : lo_t + i - 1) : (lo_t + i); };

    {
        #pragma unroll
        for (int j = 0; j < 8; j++) CP_ASYNC16(qdst[j], qsrc[j]);
        long roff = (long)kb_of(0) * 64 * E_;
        uint32_t s0 = sb + 32768;
        #pragma unroll
        for (int j = 0; j < 8; j++) CP_ASYNC16(s0 + kvdst[j], kvbase[j] + kvrow[j] + roff);
        CP_COMMIT();
        roff = (long)kb_of(1) * 64 * E_;
        uint32_t s1 = sb + 32768 + 32768;
        #pragma unroll
        for (int j = 0; j < 8; j++) CP_ASYNC16(s1 + kvdst[j], kvbase[j] + kvrow[j] + roff);
        CP_COMMIT();
    }

    const int laA = lid & 15;
    const uint32_t koChA = (uint32_t)((lid >> 4) * 16);
    const uint32_t qrow = (uint32_t)(wid*16 + laA);
    const uint32_t qxor = (qrow & 7) * 16;
    uint32_t ah[4][4], al[4][4];

    const int laB = (lid & 7) + ((lid >> 4) & 1) * 8;
    const uint32_t koChB = (uint32_t)(((lid >> 3) & 1) * 16);
    const uint32_t xorB  = (uint32_t)((lid & 7) * 16);
    const uint32_t vKeyRow = (uint32_t)(((lid >> 3) & 1)*8 + (lid & 7));
    const uint32_t vDoff   = (uint32_t)(((lid >> 4) & 1)*16);

    float o[8][4];
    #pragma unroll
    for (int nt = 0; nt < 8; nt++) { o[nt][0]=o[nt][1]=o[nt][2]=o[nt][3]=0.f; }
    float m0 = -1e30f, m1 = -1e30f, l0 = 0.f, l1 = 0.f;
    const int r0q = t0 + wid*16 + (lid >> 2);
    const int r1q = r0q + 8;

    int stage = 0;
    #pragma unroll 1
    for (int i = 0; i < nblocks; i++) {
        CP_WAIT1();
        __syncthreads();
        if (i == 0) {
            #pragma unroll
            for (int kk = 0; kk < 4; kk++) {
                uint32_t off = qrow*128 + (((uint32_t)(kk*32) + koChA) ^ qxor);
                ldmx4(ah[kk], sb + off);
                ldmx4(al[kk], sb + 16384 + off);
            }
        }
        if (i + 2 < nblocks) {
            int s2 = stage + 2; if (s2 >= 3) s2 -= 3;
            uint32_t sbase = sb + 32768 + (uint32_t)s2 * 32768;
            long roff = (long)kb_of(i + 2) * 64 * E_;
            #pragma unroll
            for (int j = 0; j < 8; j++) CP_ASYNC16(sbase + kvdst[j], kvbase[j] + kvrow[j] + roff);
        }
        CP_COMMIT();

        const int kb = kb_of(i);
        const uint32_t kvb = sb + 32768 + (uint32_t)stage * 32768;

        float s[8][4];
        #pragma unroll
        for (int nt = 0; nt < 8; nt++) { s[nt][0]=s[nt][1]=s[nt][2]=s[nt][3]=0.f; }
        #pragma unroll
        for (int kk = 0; kk < 4; kk++) {
            uint32_t bh[4][4], bl[4][4];
            #pragma unroll
            for (int g = 0; g < 4; g++) {
                uint32_t off = (uint32_t)((g*16 + laB)*128) + (((uint32_t)(kk*32) + koChB) ^ xorB);
                ldmx4(bh[g], kvb + off);
                ldmx4(bl[g], kvb + 8192 + off);
            }
            #pragma unroll
            for (int g = 0; g < 4; g++)
                #pragma unroll
                for (int hf = 0; hf < 2; hf++) {
                    int nt = g*2 + hf;
                    mma16816(s[nt], ah[kk], &bh[g][hf*2]);
                    mma16816(s[nt], ah[kk], &bl[g][hf*2]);
                    mma16816(s[nt], al[kk], &bh[g][hf*2]);
                }
        }

        // ---- pass 1 (max): mask only needed on kb>0 tiles; kb==0 tile has
        // every column global (G=64 == tile 0) so all logits stay valid.
        const bool g0 = (kb == 0);
        const int kb64 = kb * 64;
        float mr0 = -1e30f, mr1 = -1e30f;
        #pragma unroll
        for (int nt = 0; nt < 8; nt++) {
            int colb = kb64 + nt*8 + (lid & 3)*2;
            #pragma unroll
            for (int e = 0; e < 4; e++) {
                int col = colb + (e & 1);
                int tq = (e < 2) ? r0q : r1q;
                bool inb = (uint32_t)(col - tq + W_) <= (uint32_t)(2*W_);
                float se = (g0 || inb) ? s[nt][e] : -1e30f;
                s[nt][e] = se;
                if (e < 2) mr0 = fmaxf(mr0, se); else mr1 = fmaxf(mr1, se);
            }
        }
        mr0 = fmaxf(mr0, __shfl_xor_sync(0xffffffffu, mr0, 1));
        mr0 = fmaxf(mr0, __shfl_xor_sync(0xffffffffu, mr0, 2));
        mr1 = fmaxf(mr1, __shfl_xor_sync(0xffffffffu, mr1, 1));
        mr1 = fmaxf(mr1, __shfl_xor_sync(0xffffffffu, mr1, 2));
        float mn0 = fmaxf(m0, mr0), mn1 = fmaxf(m1, mr1);
        float c0 = __expf(m0 - mn0), c1 = __expf(m1 - mn1);
        l0 *= c0; l1 *= c1;
        #pragma unroll
        for (int nt = 0; nt < 8; nt++) { o[nt][0]*=c0; o[nt][1]*=c0; o[nt][2]*=c1; o[nt][3]*=c1; }

        // ---- pass 2 (weights): exp of masked (-1e30) logits is exactly 0,
        // so kb>0 tiles need NO mask math. kb==0: multiplicity 1+[in band].
        float sm0 = 0.f, sm1 = 0.f;
        if (g0) {
            #pragma unroll
            for (int nt = 0; nt < 8; nt++) {
                int colb = kb64 + nt*8 + (lid & 3)*2;
                #pragma unroll
                for (int e = 0; e < 4; e++) {
                    int col = colb + (e & 1);
                    int tq = (e < 2) ? r0q : r1q;
                    bool inb = (uint32_t)(col - tq + W_) <= (uint32_t)(2*W_);
                    float w = (inb ? 2.f : 1.f) * __expf(s[nt][e] - ((e < 2) ? mn0 : mn1));
                    s[nt][e] = w;
                    if (e < 2) sm0 += w; else sm1 += w;
                }
            }
        } else {
            #pragma unroll
            for (int nt = 0; nt < 8; nt++) {
                float w0 = __expf(s[nt][0] - mn0);
                float w1 = __expf(s[nt][1] - mn0);
                float w2 = __expf(s[nt][2] - mn1);
                float w3 = __expf(s[nt][3] - mn1);
                s[nt][0] = w0; s[nt][1] = w1; s[nt][2] = w2; s[nt][3] = w3;
                sm0 += w0 + w1; sm1 += w2 + w3;
            }
        }
        sm0 += __shfl_xor_sync(0xffffffffu, sm0, 1);
        sm0 += __shfl_xor_sync(0xffffffffu, sm0, 2);
        sm1 += __shfl_xor_sync(0xffffffffu, sm1, 1);
        sm1 += __shfl_xor_sync(0xffffffffu, sm1, 2);
        l0 += sm0; l1 += sm1; m0 = mn0; m1 = mn1;

        #pragma unroll
        for (int kk = 0; kk < 4; kk++) {
            uint32_t pah[4], pal[4];
            splitpack(s[2*kk][0],   s[2*kk][1],   pah[0], pal[0]);
            splitpack(s[2*kk][2],   s[2*kk][3],   pah[1], pal[1]);
            splitpack(s[2*kk+1][0], s[2*kk+1][1], pah[2], pal[2]);
            splitpack(s[2*kk+1][2], s[2*kk+1][3], pah[3], pal[3]);
            uint32_t vhf[4][4], vlf[4][4];
            uint32_t rowOff = (uint32_t)((kk*16 + vKeyRow) * 128);
            #pragma unroll
            for (int g = 0; g < 4; g++) {
                uint32_t off = rowOff + (((uint32_t)(g*32) + vDoff) ^ xorB);
                ldmx4t(vhf[g], kvb + 16384 + off);
                ldmx4t(vlf[g], kvb + 24576 + off);
            }
            #pragma unroll
            for (int g = 0; g < 4; g++)
                #pragma unroll
                for (int hf = 0; hf < 2; hf++) {
                    int dt = g*2 + hf;
                    mma16816(o[dt], pah, &vhf[g][hf*2]);
                    mma16816(o[dt], pah, &vlf[g][hf*2]);
                    mma16816(o[dt], pal, &vhf[g][hf*2]);
                }
        }
        stage++; if (stage >= 3) stage -= 3;
    }

    float inv0 = 1.f / l0, inv1 = 1.f / l1;
    long ob0 = ((long)(b*T_ + r0q))*E_ + hh*64;
    long ob1 = ((long)(b*T_ + r1q))*E_ + hh*64;
    #pragma unroll
    for (int dt = 0; dt < 8; dt++) {
        int col = dt*8 + (lid & 3)*2;
        uint32_t hi, lo;
        splitpack(o[dt][0]*inv0, o[dt][1]*inv0, hi, lo);
        *(uint32_t*)(ah_out + ob0 + col) = hi;
        *(uint32_t*)(al_out + ob0 + col) = lo;
        splitpack(o[dt][2]*inv1, o[dt][3]*inv1, hi, lo);
        *(uint32_t*)(ah_out + ob1 + col) = hi;
        *(uint32_t*)(al_out + ob1 + col) = lo;
    }
}

// ---------------- global-token attention (fp32, NSPLIT=8, FROZEN) --------
#define GA_SMEM (64*1024 + 1024)

__global__ __launch_bounds__(128) void gattn_partial_kernel(
    const float* __restrict__ qg, const float* __restrict__ kg,
    const float* __restrict__ vg, float* __restrict__ part)
{
    extern __shared__ char dsm_raw[];
    char* dsm = (char*)(((uintptr_t)dsm_raw + 1023) & ~(uintptr_t)1023);
    float* Ks = (float*)dsm;
    float* Vs = (float*)(dsm + 32768);

    const int tid = threadIdx.x;
    const int qi  = tid & 63;
    const int ys  = tid >> 6;
    const int split = blockIdx.x;
    const int h = blockIdx.y;
    const int b = blockIdx.z;

    float4 qr[16];
    const float4* qrow = (const float4*)(qg + ((long)(b*G_ + qi))*E_ + h*64);
    #pragma unroll
    for (int c = 0; c < 16; c++) qr[c] = qrow[c];

    float4 acc[16];
    #pragma unroll
    for (int c = 0; c < 16; c++) acc[c] = make_float4(0.f, 0.f, 0.f, 0.f);
    float mrun = -1e30f, l = 0.f;

    float* K = Ks + ys*4096;
    float* V = Vs + ys*4096;

    #pragma unroll 1
    for (int it = 0; it < 4; it++) {
        int kb = split*8 + ys*4 + it;
        #pragma unroll
        for (int j = 0; j < 16; j++) {
            int idx = qi + j*64;
            int row = idx >> 4, c4 = idx & 15;
            long base = ((long)(b*T_ + kb*64 + row))*E_ + h*64 + c4*4;
            ((float4*)K)[idx] = *(const float4*)(kg + base);
            ((float4*)V)[idx] = *(const float4*)(vg + base);
        }
        __syncthreads();
        for (int p = 0; p < 64; p++) {
            const float4* kp = (const float4*)(K + p*64);
            float s = 0.f;
            #pragma unroll
            for (int c = 0; c < 16; c++) {
                float4 kk = kp[c];
                s += qr[c].x*kk.x + qr[c].y*kk.y + qr[c].z*kk.z + qr[c].w*kk.w;
            }
            if (s > mrun) {
                float corr = __expf(mrun - s);
                l *= corr;
                #pragma unroll
                for (int c = 0; c < 16; c++) {
                    acc[c].x *= corr; acc[c].y *= corr;
                    acc[c].z *= corr; acc[c].w *= corr;
                }
                mrun = s;
            }
            float w = __expf(s - mrun);
            l += w;
            const float4* vp = (const float4*)(V + p*64);
            #pragma unroll
            for (int c = 0; c < 16; c++) {
                float4 vv = vp[c];
                acc[c].x += w*vv.x; acc[c].y += w*vv.y;
                acc[c].z += w*vv.z; acc[c].w += w*vv.w;
            }
        }
        __syncthreads();
    }

    float* buf = Vs + qi*66;
    if (ys == 1) {
        #pragma unroll
        for (int c = 0; c < 16; c++) {
            buf[c*4+0] = acc[c].x; buf[c*4+1] = acc[c].y;
            buf[c*4+2] = acc[c].z; buf[c*4+3] = acc[c].w;
        }
        buf[64] = mrun; buf[65] = l;
    }
    __syncthreads();
    if (ys == 0) {
        float m2 = buf[64], l2 = buf[65];
        float mn = fmaxf(mrun, m2);
        float w1 = __expf(mrun - mn), w2 = __expf(m2 - mn);
        float* pp = part + (((long)(b*H_ + h)*NSPLIT + split)*G_ + qi) * (D_ + 2);
        #pragma unroll
        for (int c = 0; c < 16; c++) {
            pp[c*4+0] = acc[c].x*w1 + buf[c*4+0]*w2;
            pp[c*4+1] = acc[c].y*w1 + buf[c*4+1]*w2;
            pp[c*4+2] = acc[c].z*w1 + buf[c*4+2]*w2;
            pp[c*4+3] = acc[c].w*w1 + buf[c*4+3]*w2;
        }
        pp[D_]   = mn;
        pp[D_+1] = l*w1 + l2*w2;
    }
}

__global__ __launch_bounds__(64) void gattn_combine_kernel(
    const float* __restrict__ part, bf16* __restrict__ ah_out, bf16* __restrict__ al_out)
{
    const int tid = threadIdx.x;
    const int hh  = blockIdx.x;
    const int b   = blockIdx.y;

    float M = -1e30f;
    #pragma unroll
    for (int s = 0; s < NSPLIT; s++) {
        const float* pp = part + (((long)(b*H_ + hh)*NSPLIT + s)*G_ + tid) * (D_ + 2);
        M = fmaxf(M, pp[D_]);
    }
    float L = 0.f;
    float acc[D_];
    #pragma unroll
    for (int d = 0; d < D_; d++) acc[d] = 0.f;
    for (int s = 0; s < NSPLIT; s++) {
        const float* pp = part + (((long)(b*H_ + hh)*NSPLIT + s)*G_ + tid) * (D_ + 2);
        float w = __expf(pp[D_] - M);
        L += pp[D_+1] * w;
        #pragma unroll
        for (int d = 0; d < D_; d++) acc[d] += pp[d] * w;
    }
    float inv = 1.f / L;
    long base = ((long)(b*T_ + tid))*E_ + hh*64;
    #pragma unroll
    for (int d = 0; d < D_; d += 2) {
        uint32_t hi, lo;
        splitpack(acc[d]*inv, acc[d+1]*inv, hi, lo);
        *(uint32_t*)(ah_out + base + d) = hi;
        *(uint32_t*)(al_out + base + d) = lo;
    }
}

// --------------------------------- launch --------------------------------
extern "C" void kernel_launch(void* const* d_in, const int* in_sizes, int n_in,
                              void* d_out, int out_size)
{
    const float* query = (const float*)d_in[0];
    const float* Wq  = (const float*)d_in[2];  const float* bq  = (const float*)d_in[3];
    const float* Wk  = (const float*)d_in[4];  const float* bk  = (const float*)d_in[5];
    const float* Wv  = (const float*)d_in[6];  const float* bv  = (const float*)d_in[7];
    const float* Wqg = (const float*)d_in[8];  const float* bqg = (const float*)d_in[9];
    const float* Wkg = (const float*)d_in[10]; const float* bkg = (const float*)d_in[11];
    const float* Wvg = (const float*)d_in[12]; const float* bvg = (const float*)d_in[13];
    const float* Wo  = (const float*)d_in[14]; const float* bo  = (const float*)d_in[15];
    float* out = (float*)d_out;

    bf16 *xh, *xl, *qh, *ql, *kh, *kl, *vh, *vl, *ahp, *alp, *wh, *wl;
    float *kgp, *vgp, *qgp, *partp;
    cudaGetSymbolAddress((void**)&xh,  g_xh);  cudaGetSymbolAddress((void**)&xl,  g_xl);
    cudaGetSymbolAddress((void**)&qh,  g_qh);  cudaGetSymbolAddress((void**)&ql,  g_ql);
    cudaGetSymbolAddress((void**)&kh,  g_kh);  cudaGetSymbolAddress((void**)&kl,  g_kl);
    cudaGetSymbolAddress((void**)&vh,  g_vh);  cudaGetSymbolAddress((void**)&vl,  g_vl);
    cudaGetSymbolAddress((void**)&ahp, g_ah);  cudaGetSymbolAddress((void**)&alp, g_al);
    cudaGetSymbolAddress((void**)&wh,  g_wh);  cudaGetSymbolAddress((void**)&wl,  g_wl);
    cudaGetSymbolAddress((void**)&kgp, g_kg);
    cudaGetSymbolAddress((void**)&vgp, g_vg);
    cudaGetSymbolAddress((void**)&qgp, g_qg);
    cudaGetSymbolAddress((void**)&partp, g_part);

    cudaFuncSetAttribute(gemm4_kernel,
        cudaFuncAttributeMaxDynamicSharedMemorySize, G4_SMEM);
    cudaFuncSetAttribute(qg2_kernel,
        cudaFuncAttributeMaxDynamicSharedMemorySize, QG_SMEM);
    cudaFuncSetAttribute(band2_kernel,
        cudaFuncAttributeMaxDynamicSharedMemorySize, BA2_SMEM);
    cudaFuncSetAttribute(gattn_partial_kernel,
        cudaFuncAttributeMaxDynamicSharedMemorySize, GA_SMEM);

    const float scaling = 0.125f;   // D^-0.5
    const long WSZ = (long)E_*E_;

    // ---- one-time conversions (batched, 4x ILP)
    conv_query_kernel<<<M_*E_/4/1024, 256>>>(query, xh, xl);
    {
        ConvBatch cb;
        const float* srcs[7] = {Wq, Wk, Wv, Wkg, Wvg, Wo, Wqg};
        for (int i = 0; i < 7; i++) {
            cb.src[i] = srcs[i];
            cb.oh[i]  = wh + (long)i*WSZ;
            cb.ol[i]  = wl + (long)i*WSZ;
        }
        conv_batch_kernel<<<dim3(E_*E_/4/1024, 7), 256>>>(cb);
    }
    cudaMemsetAsync(qgp, 0, (size_t)B_*G_*E_*sizeof(float));

    // ---- batched projections: q,k,v (split out) + kg,vg (fp32 out)
    {
        G3Batch bt;
        const float* biases[5] = {bq, bk, bv, bkg, bvg};
        bf16* chs[5] = {qh, kh, vh, nullptr, nullptr};
        bf16* cls[5] = {ql, kl, vl, nullptr, nullptr};
        float* cfs[5] = {nullptr, nullptr, nullptr, kgp, vgp};
        for (int i = 0; i < 5; i++) {
            bt.Ah[i] = xh; bt.Al[i] = xl;
            bt.Bh[i] = wh + (long)i*WSZ; bt.Bl[i] = wl + (long)i*WSZ;
            bt.bias[i] = biases[i];
            bt.alpha[i] = (i == 0) ? scaling : 1.f;
            bt.Cf[i] = cfs[i]; bt.Ch[i] = chs[i]; bt.Cl[i] = cls[i];
            bt.omode[i] = (i < 3) ? 2 : 0;
        }
        gemm4_kernel<<<dim3(E_/128, M_/128, 5), 256, G4_SMEM>>>(bt);
    }

    // qg projection: pre-split inputs, split-K
    qg2_kernel<<<dim3(E_/128, 8), 256, QG_SMEM>>>(xh, xl, wh+6*WSZ, wl+6*WSZ,
                                                  bqg, qgp, scaling);

    // band + global-key attention (3-stage, 1 CTA/SM)
    band2_kernel<<<dim3(T_/128, H_, B_), 256, BA2_SMEM>>>(qh, ql, kh, kl, vh, vl, ahp, alp);

    // global tokens overwrite first G rows (split out)
    gattn_partial_kernel<<<dim3(NSPLIT, H_, B_), 128, GA_SMEM>>>(qgp, kgp, vgp, partp);
    gattn_combine_kernel<<<dim3(H_, B_), 64>>>(partp, ahp, alp);

    // output projection: attn(split) @ Wo^T + bo -> fp32 [T,B,E]
    {
        G3Batch bt;
        for (int i = 0; i < 5; i++) {
            bt.Ah[i] = ahp; bt.Al[i] = alp;
            bt.Bh[i] = wh + 5*WSZ; bt.Bl[i] = wl + 5*WSZ;
            bt.bias[i] = bo; bt.alpha[i] = 1.f;
            bt.Cf[i] = out; bt.Ch[i] = nullptr; bt.Cl[i] = nullptr;
            bt.omode[i] = 1;
        }
        gemm4_kernel<<<dim3(E_/128, M_/128, 1), 256, G4_SMEM>>>(bt);
    }
}

// round 17
// speedup vs baseline: 1.0160x; 1.0160x over previous
#include <cuda_runtime.h>
#include <cuda_bf16.h>
#include <math.h>
#include <stdint.h>

#define T_ 4096
#define B_ 2
#define E_ 1024
#define H_ 16
#define D_ 64
#define W_ 256
#define G_ 64
#define M_ (B_*T_)   /* 8192 */
#define NSPLIT 8

typedef __nv_bfloat16 bf16;

// ---------------- scratch (device globals; no allocation) ----------------
__device__ bf16 g_xh[M_*E_];   // converted query (transposed to [B*T,E])
__device__ bf16 g_xl[M_*E_];
__device__ bf16 g_qh[M_*E_],  g_ql[M_*E_];
__device__ bf16 g_kh[M_*E_],  g_kl[M_*E_];
__device__ bf16 g_vh[M_*E_],  g_vl[M_*E_];
__device__ bf16 g_ah[M_*E_],  g_al[M_*E_];        // attention output (split)
__device__ bf16 g_wh[7*E_*E_], g_wl[7*E_*E_];      // Wq,Wk,Wv,Wkg,Wvg,Wo,Wqg
__device__ float g_kg[M_*E_];
__device__ float g_vg[M_*E_];
__device__ float g_qg[B_*G_*E_];
__device__ float g_part[(long)B_*H_*NSPLIT*G_*(D_+2)];

// ------------------------------ helpers ----------------------------------
__device__ __forceinline__ uint32_t smem_to_u32(const void* p) {
    uint32_t a;
    asm("{ .reg .u64 t; cvta.to.shared.u64 t, %1; cvt.u32.u64 %0, t; }"
        : "=r"(a) : "l"(p));
    return a;
}
#define SMEM_SWIZZLE_128B(o) ((o) ^ (((o) >> 3) & 0x70))
#define SMEM_SWIZZLE_64B(o)  ((o) ^ (((o) >> 3) & 0x30))

#define CP_ASYNC16(dst, src) \
    asm volatile("cp.async.cg.shared.global [%0], [%1], 16;" :: "r"(dst), "l"(src))
#define CP_COMMIT() asm volatile("cp.async.commit_group;" ::: "memory")
#define CP_WAIT1()  asm volatile("cp.async.wait_group 1;" ::: "memory")
#define CP_WAIT0()  asm volatile("cp.async.wait_group 0;" ::: "memory")

__device__ __forceinline__ void ldmx4(uint32_t* r, uint32_t addr) {
    asm volatile("ldmatrix.sync.aligned.m8n8.x4.shared.b16 {%0,%1,%2,%3}, [%4];"
        : "=r"(r[0]), "=r"(r[1]), "=r"(r[2]), "=r"(r[3]) : "r"(addr));
}
__device__ __forceinline__ void ldmx4t(uint32_t* r, uint32_t addr) {
    asm volatile("ldmatrix.sync.aligned.m8n8.x4.trans.shared.b16 {%0,%1,%2,%3}, [%4];"
        : "=r"(r[0]), "=r"(r[1]), "=r"(r[2]), "=r"(r[3]) : "r"(addr));
}
__device__ __forceinline__ void mma16816(float* d, const uint32_t* a, const uint32_t* b) {
    asm volatile("mma.sync.aligned.m16n8k16.row.col.f32.bf16.bf16.f32 "
        "{%0,%1,%2,%3}, {%4,%5,%6,%7}, {%8,%9}, {%0,%1,%2,%3};"
        : "+f"(d[0]), "+f"(d[1]), "+f"(d[2]), "+f"(d[3])
        : "r"(a[0]), "r"(a[1]), "r"(a[2]), "r"(a[3]), "r"(b[0]), "r"(b[1]));
}

__device__ __forceinline__ void split4(float4 v, uint2& hi, uint2& lo) {
    __nv_bfloat162 h0 = __float22bfloat162_rn(make_float2(v.x, v.y));
    __nv_bfloat162 h1 = __float22bfloat162_rn(make_float2(v.z, v.w));
    float2 f0 = __bfloat1622float2(h0);
    float2 f1 = __bfloat1622float2(h1);
    __nv_bfloat162 l0 = __float22bfloat162_rn(make_float2(v.x - f0.x, v.y - f0.y));
    __nv_bfloat162 l1 = __float22bfloat162_rn(make_float2(v.z - f1.x, v.w - f1.y));
    hi.x = *(uint32_t*)&h0; hi.y = *(uint32_t*)&h1;
    lo.x = *(uint32_t*)&l0; lo.y = *(uint32_t*)&l1;
}
__device__ __forceinline__ void splitpack(float a, float b, uint32_t& hi, uint32_t& lo) {
    __nv_bfloat162 h = __float22bfloat162_rn(make_float2(a, b));
    float2 f = __bfloat1622float2(h);
    __nv_bfloat162 l2 = __float22bfloat162_rn(make_float2(a - f.x, b - f.y));
    hi = *(uint32_t*)&h; lo = *(uint32_t*)&l2;
}

// -------------------- one-time split conversions (4x ILP) -----------------
struct ConvBatch {
    const float* src[7];
    bf16* oh[7];
    bf16* ol[7];
};
__global__ __launch_bounds__(256) void conv_batch_kernel(ConvBatch cb)
{
    int z = blockIdx.y;
    const float4* src = (const float4*)cb.src[z];
    uint2* oh = (uint2*)cb.oh[z];
    uint2* ol = (uint2*)cb.ol[z];
    int base = blockIdx.x*1024 + threadIdx.x;
    float4 v[4];
    #pragma unroll
    for (int u = 0; u < 4; u++) v[u] = src[base + u*256];
    #pragma unroll
    for (int u = 0; u < 4; u++) {
        uint2 h, l; split4(v[u], h, l);
        oh[base + u*256] = h; ol[base + u*256] = l;
    }
}
// query [T,B,E] fp32 -> [B*T,E] split bf16
__global__ __launch_bounds__(256) void conv_query_kernel(
    const float* __restrict__ q, bf16* __restrict__ oh, bf16* __restrict__ ol)
{
    int base = blockIdx.x*1024 + threadIdx.x;
    float4 v[4];
    #pragma unroll
    for (int u = 0; u < 4; u++) {
        int i = base + u*256;
        int m = i >> 8, c = i & 255;
        int b = m >> 12, t = m & 4095;
        v[u] = ((const float4*)q)[(t*B_ + b)*256 + c];
    }
    #pragma unroll
    for (int u = 0; u < 4; u++) {
        int i = base + u*256;
        uint2 h, l; split4(v[u], h, l);
        ((uint2*)oh)[i] = h; ((uint2*)ol)[i] = l;
    }
}

// === batched GEMM v4 (champion): K=32 chunks (SW64), 3 stages ===========
#define G4_STAGE 32768
#define G4_SMEM  (3*G4_STAGE + 1024)
#define G3_NB 5

struct G3Batch {
    const bf16* Ah[G3_NB]; const bf16* Al[G3_NB];
    const bf16* Bh[G3_NB]; const bf16* Bl[G3_NB];
    const float* bias[G3_NB];
    float alpha[G3_NB];
    float* Cf[G3_NB];
    bf16* Ch[G3_NB]; bf16* Cl[G3_NB];
    int omode[G3_NB];
};

__global__ __launch_bounds__(256, 2) void gemm4_kernel(G3Batch bt)
{
    extern __shared__ char dsm_raw[];
    char* dsm = (char*)(((uintptr_t)dsm_raw + 1023) & ~(uintptr_t)1023);
    const uint32_t sb = smem_to_u32(dsm);

    const int z = blockIdx.z;
    const int tid = threadIdx.x;
    const int wid = tid >> 5;
    const int lid = tid & 31;
    const int m0  = blockIdx.y * 128;
    const int n0  = blockIdx.x * 128;
    const int wm  = wid & 3;
    const int wn  = wid >> 2;

    // ---- cp.async: 8 transfers/thread/stage; stage layout:
    // Ah @0, Al @8192, Bh @16384, Bl @24576  (each 128 rows x 64B, SW64)
    const bf16* gptr[8];
    uint32_t dst_rel[8];
    {
        const bf16* Abase[2] = { bt.Ah[z], bt.Al[z] };
        const bf16* Bbase[2] = { bt.Bh[z], bt.Bl[z] };
        #pragma unroll
        for (int j = 0; j < 8; j++) {
            int idx = tid + j*256;
            int mat = idx >> 9;           // 0..3
            int e   = idx & 511;
            int r   = e >> 2, ch = e & 3;
            long row = (mat < 2) ? (long)(m0 + r) : (long)(n0 + r);
            const bf16* base = (mat < 2) ? Abase[mat] : Bbase[mat - 2];
            gptr[j] = base + row*E_ + ch*8;
            dst_rel[j] = (uint32_t)(mat*8192) + SMEM_SWIZZLE_64B((uint32_t)(r*64 + ch*16));
        }
    }

    // ---- ldmatrix lane constants (SW64: xor = ((la>>1)&3)*16, lane-only)
    const int laA = lid & 15;
    const uint32_t koChA = (uint32_t)((lid >> 4) * 16);
    const uint32_t xorA  = (uint32_t)(((laA >> 1) & 3) * 16);
    const uint32_t rowA0 = (uint32_t)((wm*32 + laA) * 64);
    const int laB = (lid & 7) + ((lid >> 4) & 1) * 8;
    const uint32_t koChB = (uint32_t)(((lid >> 3) & 1) * 16);
    const uint32_t xorB  = (uint32_t)(((laB >> 1) & 3) * 16);
    const uint32_t rowB0 = (uint32_t)((wn*64 + laB) * 64);

    float acc[2][8][4];
    #pragma unroll
    for (int mt = 0; mt < 2; mt++)
        #pragma unroll
        for (int nt = 0; nt < 8; nt++)
            #pragma unroll
            for (int e = 0; e < 4; e++) acc[mt][nt][e] = 0.f;

    // prologue: stages 0,1 (chunks 0,1)
    #pragma unroll
    for (int p = 0; p < 2; p++) {
        const uint32_t base = sb + (uint32_t)p * G4_STAGE;
        #pragma unroll
        for (int j = 0; j < 8; j++) {
            CP_ASYNC16(base + dst_rel[j], gptr[j]);
            gptr[j] += 32;
        }
        CP_COMMIT();
    }

    int stage = 0;
    #pragma unroll 1
    for (int c = 0; c < 32; c++) {
        CP_WAIT1();
        __syncthreads();
        if (c + 2 < 32) {
            int s2 = stage + 2; if (s2 >= 3) s2 -= 3;
            const uint32_t base = sb + (uint32_t)s2 * G4_STAGE;
            #pragma unroll
            for (int j = 0; j < 8; j++) {
                CP_ASYNC16(base + dst_rel[j], gptr[j]);
                gptr[j] += 32;
            }
        }
        CP_COMMIT();

        const uint32_t st = sb + (uint32_t)stage * G4_STAGE;
        #pragma unroll
        for (int k16 = 0; k16 < 2; k16++) {
            const uint32_t koA = (uint32_t)(k16*32) + koChA;
            const uint32_t koB = (uint32_t)(k16*32) + koChB;
            uint32_t bh[4][4];
            #pragma unroll
            for (int g = 0; g < 4; g++)
                ldmx4(bh[g], st + 16384 + rowB0 + (uint32_t)(g*1024) + (koB ^ xorB));
            uint32_t ah[2][4];
            #pragma unroll
            for (int mt = 0; mt < 2; mt++)
                ldmx4(ah[mt], st + rowA0 + (uint32_t)(mt*1024) + (koA ^ xorA));
            #pragma unroll
            for (int mt = 0; mt < 2; mt++)
                #pragma unroll
                for (int nt = 0; nt < 8; nt++)
                    mma16816(acc[mt][nt], ah[mt], &bh[nt >> 1][(nt & 1)*2]);
            uint32_t al[2][4];
            #pragma unroll
            for (int mt = 0; mt < 2; mt++)
                ldmx4(al[mt], st + 8192 + rowA0 + (uint32_t)(mt*1024) + (koA ^ xorA));
            #pragma unroll
            for (int mt = 0; mt < 2; mt++)
                #pragma unroll
                for (int nt = 0; nt < 8; nt++)
                    mma16816(acc[mt][nt], al[mt], &bh[nt >> 1][(nt & 1)*2]);
            uint32_t bl[4][4];
            #pragma unroll
            for (int g = 0; g < 4; g++)
                ldmx4(bl[g], st + 24576 + rowB0 + (uint32_t)(g*1024) + (koB ^ xorB));
            #pragma unroll
            for (int mt = 0; mt < 2; mt++)
                #pragma unroll
                for (int nt = 0; nt < 8; nt++)
                    mma16816(acc[mt][nt], ah[mt], &bl[nt >> 1][(nt & 1)*2]);
        }
        stage++; if (stage >= 3) stage -= 3;
    }

    // ---- epilogue
    const int omode = bt.omode[z];
    const float alpha = bt.alpha[z];
    const float* __restrict__ bias = bt.bias[z];
    const int qrow = lid >> 2;
    const int qcol = (lid & 3) * 2;
    #pragma unroll
    for (int mt = 0; mt < 2; mt++) {
        #pragma unroll
        for (int half = 0; half < 2; half++) {
            long m = m0 + wm*32 + mt*16 + qrow + half*8;
            long obase;
            if (omode == 1) { long b = m >> 12, t = m & 4095; obase = (t*B_ + b)*(long)E_; }
            else            { obase = m * (long)E_; }
            #pragma unroll
            for (int nt = 0; nt < 8; nt++) {
                int col = n0 + wn*64 + nt*8 + qcol;
                float2 bi = *(const float2*)&bias[col];
                float v0 = (acc[mt][nt][half*2+0] + bi.x) * alpha;
                float v1 = (acc[mt][nt][half*2+1] + bi.y) * alpha;
                if (omode == 2) {
                    uint32_t hi, lo; splitpack(v0, v1, hi, lo);
                    *(uint32_t*)(bt.Ch[z] + obase + col) = hi;
                    *(uint32_t*)(bt.Cl[z] + obase + col) = lo;
                } else {
                    *(float2*)(bt.Cf[z] + obase + col) = make_float2(v0, v1);
                }
            }
        }
    }
}

// ======= qg projection v2 (champion): pre-split inputs, split-K ==========
#define G3_STAGE 65536
#define QG_SMEM (2*G3_STAGE + 1024)

__global__ __launch_bounds__(256, 1) void qg2_kernel(
    const bf16* __restrict__ Ah, const bf16* __restrict__ Al,
    const bf16* __restrict__ Bh, const bf16* __restrict__ Bl,
    const float* __restrict__ bias, float* __restrict__ C, float alpha)
{
    extern __shared__ char dsm_raw[];
    char* dsm = (char*)(((uintptr_t)dsm_raw + 1023) & ~(uintptr_t)1023);
    const uint32_t sb = smem_to_u32(dsm);

    const int tid = threadIdx.x;
    const int wid = tid >> 5;
    const int lid = tid & 31;
    const int n0  = blockIdx.x * 128;
    const int ks  = blockIdx.y;          // k slice 0..7 (128 K each)
    const int wm  = wid & 3;
    const int wn  = wid >> 2;

    uint32_t dsw[4]; long aoff[4], boff[4];
    #pragma unroll
    for (int j = 0; j < 4; j++) {
        int idx = tid + j*256;
        int r = idx >> 3, ch = idx & 7;
        dsw[j]  = SMEM_SWIZZLE_128B((uint32_t)(r*128 + ch*16));
        long b = r >> 6, t = r & 63;
        aoff[j] = (b*T_ + t)*(long)E_ + ks*128 + ch*8;
        boff[j] = (long)(n0 + r)*E_ + ks*128 + ch*8;
    }

    const int laA = lid & 15;
    const uint32_t koChA = (uint32_t)((lid >> 4) * 16);
    uint32_t rowA[2], xorA[2];
    #pragma unroll
    for (int mt = 0; mt < 2; mt++) {
        int r = wm*32 + mt*16 + laA;
        rowA[mt] = (uint32_t)(r * 128);
        xorA[mt] = (uint32_t)((r & 7) * 16);
    }
    const int laB = (lid & 7) + ((lid >> 4) & 1) * 8;
    const uint32_t koChB = (uint32_t)(((lid >> 3) & 1) * 16);
    uint32_t rowB[4], xorB[4];
    #pragma unroll
    for (int g = 0; g < 4; g++) {
        int r = wn*64 + g*16 + laB;
        rowB[g] = (uint32_t)(r * 128);
        xorB[g] = (uint32_t)((r & 7) * 16);
    }

    float acc[2][8][4];
    #pragma unroll
    for (int mt = 0; mt < 2; mt++)
        #pragma unroll
        for (int nt = 0; nt < 8; nt++)
            #pragma unroll
            for (int e = 0; e < 4; e++) acc[mt][nt][e] = 0.f;

    #pragma unroll
    for (int p = 0; p < 2; p++) {
        const uint32_t base = sb + (uint32_t)p * G3_STAGE;
        const long k0 = (long)p * 64;
        #pragma unroll
        for (int j = 0; j < 4; j++) CP_ASYNC16(base + dsw[j],         Ah + aoff[j] + k0);
        #pragma unroll
        for (int j = 0; j < 4; j++) CP_ASYNC16(base + 16384 + dsw[j], Al + aoff[j] + k0);
        #pragma unroll
        for (int j = 0; j < 4; j++) CP_ASYNC16(base + 32768 + dsw[j], Bh + boff[j] + k0);
        #pragma unroll
        for (int j = 0; j < 4; j++) CP_ASYNC16(base + 49152 + dsw[j], Bl + boff[j] + k0);
        CP_COMMIT();
    }
    CP_WAIT0();
    __syncthreads();

    #pragma unroll
    for (int c = 0; c < 2; c++) {
        const uint32_t bAh = sb + (uint32_t)c * G3_STAGE;
        const uint32_t bAl = bAh + 16384;
        const uint32_t bBh = bAh + 32768;
        const uint32_t bBl = bAh + 49152;
        #pragma unroll
        for (int k16 = 0; k16 < 4; k16++) {
            const uint32_t koA = (uint32_t)(k16*32) + koChA;
            const uint32_t koB = (uint32_t)(k16*32) + koChB;
            uint32_t ah[2][4], al[2][4];
            #pragma unroll
            for (int mt = 0; mt < 2; mt++) {
                uint32_t off = rowA[mt] + (koA ^ xorA[mt]);
                ldmx4(ah[mt], bAh + off);
                ldmx4(al[mt], bAl + off);
            }
            uint32_t bh[4][4], bl[4][4];
            #pragma unroll
            for (int g = 0; g < 4; g++) {
                uint32_t off = rowB[g] + (koB ^ xorB[g]);
                ldmx4(bh[g], bBh + off);
                ldmx4(bl[g], bBl + off);
            }
            #pragma unroll
            for (int mt = 0; mt < 2; mt++)
                #pragma unroll
                for (int nt = 0; nt < 8; nt++) {
                    const int g = nt >> 1, hf = (nt & 1) * 2;
                    mma16816(acc[mt][nt], ah[mt], &bh[g][hf]);
                    mma16816(acc[mt][nt], ah[mt], &bl[g][hf]);
                    mma16816(acc[mt][nt], al[mt], &bh[g][hf]);
                }
        }
    }

    const int qrow = lid >> 2;
    const int qcol = (lid & 3) * 2;
    #pragma unroll
    for (int mt = 0; mt < 2; mt++)
        #pragma unroll
        for (int half = 0; half < 2; half++) {
            long m = wm*32 + mt*16 + qrow + half*8;
            #pragma unroll
            for (int nt = 0; nt < 8; nt++) {
                int col = n0 + wn*64 + nt*8 + qcol;
                float v0 = acc[mt][nt][half*2+0];
                float v1 = acc[mt][nt][half*2+1];
                if (ks == 0) { v0 += bias[col]; v1 += bias[col+1]; }
                atomicAdd(&C[m*E_ + col],     v0 * alpha);
                atomicAdd(&C[m*E_ + col + 1], v1 * alpha);
            }
        }
}

// ======== band + global-key attention v2 (champion) ======================
#define BA2_SMEM (32768 + 3*32768 + 1024)

__global__ __launch_bounds__(256, 1) void band2_kernel(
    const bf16* __restrict__ qh, const bf16* __restrict__ ql,
    const bf16* __restrict__ kh, const bf16* __restrict__ kl,
    const bf16* __restrict__ vh, const bf16* __restrict__ vl,
    bf16* __restrict__ ah_out, bf16* __restrict__ al_out)
{
    extern __shared__ char dsm_raw[];
    char* dsm = (char*)(((uintptr_t)dsm_raw + 1023) & ~(uintptr_t)1023);
    const uint32_t sb = smem_to_u32(dsm);
    const int tid = threadIdx.x, wid = tid >> 5, lid = tid & 31;
    const int qt = blockIdx.x, hh = blockIdx.y, b = blockIdx.z;
    const int t0 = qt * 128;

    const bf16* qsrc[8]; uint32_t qdst[8];
    #pragma unroll
    for (int j = 0; j < 8; j++) {
        int idx = tid + j*256;
        int mq = idx >> 10, r = (idx >> 3) & 127, ch = idx & 7;
        qsrc[j] = (mq ? ql : qh) + ((long)(b*T_ + t0 + r))*E_ + hh*64 + ch*8;
        qdst[j] = sb + (uint32_t)(mq*16384) + SMEM_SWIZZLE_128B((uint32_t)(r*128 + ch*16));
    }
    const bf16* kvbase[8]; long kvrow[8]; uint32_t kvdst[8];
    #pragma unroll
    for (int j = 0; j < 8; j++) {
        int idx = tid + j*256;
        int mat = idx >> 9, r = (idx >> 3) & 63, ch = idx & 7;
        const bf16* p = (mat < 2) ? (mat == 0 ? kh : kl) : (mat == 2 ? vh : vl);
        kvbase[j] = p + ((long)(b*T_))*E_ + hh*64 + ch*8;
        kvrow[j]  = (long)r * E_;
        kvdst[j]  = (uint32_t)(mat*8192) + SMEM_SWIZZLE_128B((uint32_t)(r*128 + ch*16));
    }

    const int lo_t = (qt*2-4 > 0) ? qt*2-4 : 0;
    int hi_t = qt*2 + 5; if (hi_t > 63) hi_t = 63;
    const int extra = (lo_t > 0) ? 1 : 0;
    const int nblocks = hi_t - lo_t + 1 + extra;

    auto kb_of = [&](int i) { return extra ? ((i == 0) ? 0 : lo_t + i - 1) : (lo_t + i); };

    {
        #pragma unroll
        for (int j = 0; j < 8; j++) CP_ASYNC16(qdst[j], qsrc[j]);
        long roff = (long)kb_of(0) * 64 * E_;
        uint32_t s0 = sb + 32768;
        #pragma unroll
        for (int j = 0; j < 8; j++) CP_ASYNC16(s0 + kvdst[j], kvbase[j] + kvrow[j] + roff);
        CP_COMMIT();
        roff = (long)kb_of(1) * 64 * E_;
        uint32_t s1 = sb + 32768 + 32768;
        #pragma unroll
        for (int j = 0; j < 8; j++) CP_ASYNC16(s1 + kvdst[j], kvbase[j] + kvrow[j] + roff);
        CP_COMMIT();
    }

    const int laA = lid & 15;
    const uint32_t koChA = (uint32_t)((lid >> 4) * 16);
    const uint32_t qrow = (uint32_t)(wid*16 + laA);
    const uint32_t qxor = (qrow & 7) * 16;
    uint32_t ah[4][4], al[4][4];

    const int laB = (lid & 7) + ((lid >> 4) & 1) * 8;
    const uint32_t koChB = (uint32_t)(((lid >> 3) & 1) * 16);
    const uint32_t xorB  = (uint32_t)((lid & 7) * 16);
    const uint32_t vKeyRow = (uint32_t)(((lid >> 3) & 1)*8 + (lid & 7));
    const uint32_t vDoff   = (uint32_t)(((lid >> 4) & 1)*16);

    float o[8][4];
    #pragma unroll
    for (int nt = 0; nt < 8; nt++) { o[nt][0]=o[nt][1]=o[nt][2]=o[nt][3]=0.f; }
    float m0 = -1e30f, m1 = -1e30f, l0 = 0.f, l1 = 0.f;
    const int r0q = t0 + wid*16 + (lid >> 2);
    const int r1q = r0q + 8;

    int stage = 0;
    #pragma unroll 1
    for (int i = 0; i < nblocks; i++) {
        CP_WAIT1();
        __syncthreads();
        if (i == 0) {
            #pragma unroll
            for (int kk = 0; kk < 4; kk++) {
                uint32_t off = qrow*128 + (((uint32_t)(kk*32) + koChA) ^ qxor);
                ldmx4(ah[kk], sb + off);
                ldmx4(al[kk], sb + 16384 + off);
            }
        }
        if (i + 2 < nblocks) {
            int s2 = stage + 2; if (s2 >= 3) s2 -= 3;
            uint32_t sbase = sb + 32768 + (uint32_t)s2 * 32768;
            long roff = (long)kb_of(i + 2) * 64 * E_;
            #pragma unroll
            for (int j = 0; j < 8; j++) CP_ASYNC16(sbase + kvdst[j], kvbase[j] + kvrow[j] + roff);
        }
        CP_COMMIT();

        const int kb = kb_of(i);
        const uint32_t kvb = sb + 32768 + (uint32_t)stage * 32768;

        float s[8][4];
        #pragma unroll
        for (int nt = 0; nt < 8; nt++) { s[nt][0]=s[nt][1]=s[nt][2]=s[nt][3]=0.f; }
        #pragma unroll
        for (int kk = 0; kk < 4; kk++) {
            uint32_t bh[4][4], bl[4][4];
            #pragma unroll
            for (int g = 0; g < 4; g++) {
                uint32_t off = (uint32_t)((g*16 + laB)*128) + (((uint32_t)(kk*32) + koChB) ^ xorB);
                ldmx4(bh[g], kvb + off);
                ldmx4(bl[g], kvb + 8192 + off);
            }
            #pragma unroll
            for (int g = 0; g < 4; g++)
                #pragma unroll
                for (int hf = 0; hf < 2; hf++) {
                    int nt = g*2 + hf;
                    mma16816(s[nt], ah[kk], &bh[g][hf*2]);
                    mma16816(s[nt], ah[kk], &bl[g][hf*2]);
                    mma16816(s[nt], al[kk], &bh[g][hf*2]);
                }
        }

        const int kb64 = kb * 64;
        float mr0 = -1e30f, mr1 = -1e30f;
        #pragma unroll
        for (int nt = 0; nt < 8; nt++) {
            int colb = kb64 + nt*8 + (lid & 3)*2;
            #pragma unroll
            for (int e = 0; e < 4; e++) {
                int col = colb + (e & 1);
                int tq = (e < 2) ? r0q : r1q;
                int dlt = col - tq;
                int mlt = ((col < G_) ? 1 : 0) + ((dlt >= -W_ && dlt <= W_) ? 1 : 0);
                float se = (mlt > 0) ? s[nt][e] : -1e30f;
                s[nt][e] = se;
                if (e < 2) mr0 = fmaxf(mr0, se); else mr1 = fmaxf(mr1, se);
            }
        }
        mr0 = fmaxf(mr0, __shfl_xor_sync(0xffffffffu, mr0, 1));
        mr0 = fmaxf(mr0, __shfl_xor_sync(0xffffffffu, mr0, 2));
        mr1 = fmaxf(mr1, __shfl_xor_sync(0xffffffffu, mr1, 1));
        mr1 = fmaxf(mr1, __shfl_xor_sync(0xffffffffu, mr1, 2));
        float mn0 = fmaxf(m0, mr0), mn1 = fmaxf(m1, mr1);
        float c0 = __expf(m0 - mn0), c1 = __expf(m1 - mn1);
        l0 *= c0; l1 *= c1;
        #pragma unroll
        for (int nt = 0; nt < 8; nt++) { o[nt][0]*=c0; o[nt][1]*=c0; o[nt][2]*=c1; o[nt][3]*=c1; }

        float sm0 = 0.f, sm1 = 0.f;
        #pragma unroll
        for (int nt = 0; nt < 8; nt++) {
            int colb = kb64 + nt*8 + (lid & 3)*2;
            #pragma unroll
            for (int e = 0; e < 4; e++) {
                int col = colb + (e & 1);
                int tq = (e < 2) ? r0q : r1q;
                int dlt = col - tq;
                float mlt = (float)(((col < G_) ? 1 : 0) + ((dlt >= -W_ && dlt <= W_) ? 1 : 0));
                float w = mlt * __expf(s[nt][e] - ((e < 2) ? mn0 : mn1));
                s[nt][e] = w;
                if (e < 2) sm0 += w; else sm1 += w;
            }
        }
        sm0 += __shfl_xor_sync(0xffffffffu, sm0, 1);
        sm0 += __shfl_xor_sync(0xffffffffu, sm0, 2);
        sm1 += __shfl_xor_sync(0xffffffffu, sm1, 1);
        sm1 += __shfl_xor_sync(0xffffffffu, sm1, 2);
        l0 += sm0; l1 += sm1; m0 = mn0; m1 = mn1;

        #pragma unroll
        for (int kk = 0; kk < 4; kk++) {
            uint32_t pah[4], pal[4];
            splitpack(s[2*kk][0],   s[2*kk][1],   pah[0], pal[0]);
            splitpack(s[2*kk][2],   s[2*kk][3],   pah[1], pal[1]);
            splitpack(s[2*kk+1][0], s[2*kk+1][1], pah[2], pal[2]);
            splitpack(s[2*kk+1][2], s[2*kk+1][3], pah[3], pal[3]);
            uint32_t vhf[4][4], vlf[4][4];
            uint32_t rowOff = (uint32_t)((kk*16 + vKeyRow) * 128);
            #pragma unroll
            for (int g = 0; g < 4; g++) {
                uint32_t off = rowOff + (((uint32_t)(g*32) + vDoff) ^ xorB);
                ldmx4t(vhf[g], kvb + 16384 + off);
                ldmx4t(vlf[g], kvb + 24576 + off);
            }
            #pragma unroll
            for (int g = 0; g < 4; g++)
                #pragma unroll
                for (int hf = 0; hf < 2; hf++) {
                    int dt = g*2 + hf;
                    mma16816(o[dt], pah, &vhf[g][hf*2]);
                    mma16816(o[dt], pah, &vlf[g][hf*2]);
                    mma16816(o[dt], pal, &vhf[g][hf*2]);
                }
        }
        stage++; if (stage >= 3) stage -= 3;
    }

    float inv0 = 1.f / l0, inv1 = 1.f / l1;
    long ob0 = ((long)(b*T_ + r0q))*E_ + hh*64;
    long ob1 = ((long)(b*T_ + r1q))*E_ + hh*64;
    #pragma unroll
    for (int dt = 0; dt < 8; dt++) {
        int col = dt*8 + (lid & 3)*2;
        uint32_t hi, lo;
        splitpack(o[dt][0]*inv0, o[dt][1]*inv0, hi, lo);
        *(uint32_t*)(ah_out + ob0 + col) = hi;
        *(uint32_t*)(al_out + ob0 + col) = lo;
        splitpack(o[dt][2]*inv1, o[dt][3]*inv1, hi, lo);
        *(uint32_t*)(ah_out + ob1 + col) = hi;
        *(uint32_t*)(al_out + ob1 + col) = lo;
    }
}

// ---------------- global-token attention (fp32, NSPLIT=8) ----------------
#define GA_SMEM (64*1024 + 1024)

__global__ __launch_bounds__(128) void gattn_partial_kernel(
    const float* __restrict__ qg, const float* __restrict__ kg,
    const float* __restrict__ vg, float* __restrict__ part)
{
    extern __shared__ char dsm_raw[];
    char* dsm = (char*)(((uintptr_t)dsm_raw + 1023) & ~(uintptr_t)1023);
    float* Ks = (float*)dsm;
    float* Vs = (float*)(dsm + 32768);

    const int tid = threadIdx.x;
    const int qi  = tid & 63;
    const int ys  = tid >> 6;
    const int split = blockIdx.x;
    const int h = blockIdx.y;
    const int b = blockIdx.z;

    float4 qr[16];
    const float4* qrow = (const float4*)(qg + ((long)(b*G_ + qi))*E_ + h*64);
    #pragma unroll
    for (int c = 0; c < 16; c++) qr[c] = qrow[c];

    float4 acc[16];
    #pragma unroll
    for (int c = 0; c < 16; c++) acc[c] = make_float4(0.f, 0.f, 0.f, 0.f);
    float mrun = -1e30f, l = 0.f;

    float* K = Ks + ys*4096;
    float* V = Vs + ys*4096;

    #pragma unroll 1
    for (int it = 0; it < 4; it++) {
        int kb = split*8 + ys*4 + it;
        #pragma unroll
        for (int j = 0; j < 16; j++) {
            int idx = qi + j*64;
            int row = idx >> 4, c4 = idx & 15;
            long base = ((long)(b*T_ + kb*64 + row))*E_ + h*64 + c4*4;
            ((float4*)K)[idx] = *(const float4*)(kg + base);
            ((float4*)V)[idx] = *(const float4*)(vg + base);
        }
        __syncthreads();
        for (int p = 0; p < 64; p++) {
            const float4* kp = (const float4*)(K + p*64);
            float s = 0.f;
            #pragma unroll
            for (int c = 0; c < 16; c++) {
                float4 kk = kp[c];
                s += qr[c].x*kk.x + qr[c].y*kk.y + qr[c].z*kk.z + qr[c].w*kk.w;
            }
            if (s > mrun) {
                float corr = __expf(mrun - s);
                l *= corr;
                #pragma unroll
                for (int c = 0; c < 16; c++) {
                    acc[c].x *= corr; acc[c].y *= corr;
                    acc[c].z *= corr; acc[c].w *= corr;
                }
                mrun = s;
            }
            float w = __expf(s - mrun);
            l += w;
            const float4* vp = (const float4*)(V + p*64);
            #pragma unroll
            for (int c = 0; c < 16; c++) {
                float4 vv = vp[c];
                acc[c].x += w*vv.x; acc[c].y += w*vv.y;
                acc[c].z += w*vv.z; acc[c].w += w*vv.w;
            }
        }
        __syncthreads();
    }

    float* buf = Vs + qi*66;
    if (ys == 1) {
        #pragma unroll
        for (int c = 0; c < 16; c++) {
            buf[c*4+0] = acc[c].x; buf[c*4+1] = acc[c].y;
            buf[c*4+2] = acc[c].z; buf[c*4+3] = acc[c].w;
        }
        buf[64] = mrun; buf[65] = l;
    }
    __syncthreads();
    if (ys == 0) {
        float m2 = buf[64], l2 = buf[65];
        float mn = fmaxf(mrun, m2);
        float w1 = __expf(mrun - mn), w2 = __expf(m2 - mn);
        float* pp = part + (((long)(b*H_ + h)*NSPLIT + split)*G_ + qi) * (D_ + 2);
        #pragma unroll
        for (int c = 0; c < 16; c++) {
            pp[c*4+0] = acc[c].x*w1 + buf[c*4+0]*w2;
            pp[c*4+1] = acc[c].y*w1 + buf[c*4+1]*w2;
            pp[c*4+2] = acc[c].z*w1 + buf[c*4+2]*w2;
            pp[c*4+3] = acc[c].w*w1 + buf[c*4+3]*w2;
        }
        pp[D_]   = mn;
        pp[D_+1] = l*w1 + l2*w2;
    }
}

__global__ __launch_bounds__(64) void gattn_combine_kernel(
    const float* __restrict__ part, bf16* __restrict__ ah_out, bf16* __restrict__ al_out)
{
    const int tid = threadIdx.x;
    const int hh  = blockIdx.x;
    const int b   = blockIdx.y;

    float M = -1e30f;
    #pragma unroll
    for (int s = 0; s < NSPLIT; s++) {
        const float* pp = part + (((long)(b*H_ + hh)*NSPLIT + s)*G_ + tid) * (D_ + 2);
        M = fmaxf(M, pp[D_]);
    }
    float L = 0.f;
    float acc[D_];
    #pragma unroll
    for (int d = 0; d < D_; d++) acc[d] = 0.f;
    for (int s = 0; s < NSPLIT; s++) {
        const float* pp = part + (((long)(b*H_ + hh)*NSPLIT + s)*G_ + tid) * (D_ + 2);
        float w = __expf(pp[D_] - M);
        L += pp[D_+1] * w;
        #pragma unroll
        for (int d = 0; d < D_; d++) acc[d] += pp[d] * w;
    }
    float inv = 1.f / L;
    long base = ((long)(b*T_ + tid))*E_ + hh*64;
    #pragma unroll
    for (int d = 0; d < D_; d += 2) {
        uint32_t hi, lo;
        splitpack(acc[d]*inv, acc[d+1]*inv, hi, lo);
        *(uint32_t*)(ah_out + base + d) = hi;
        *(uint32_t*)(al_out + base + d) = lo;
    }
}

// --------------------------------- launch --------------------------------
extern "C" void kernel_launch(void* const* d_in, const int* in_sizes, int n_in,
                              void* d_out, int out_size)
{
    const float* query = (const float*)d_in[0];
    const float* Wq  = (const float*)d_in[2];  const float* bq  = (const float*)d_in[3];
    const float* Wk  = (const float*)d_in[4];  const float* bk  = (const float*)d_in[5];
    const float* Wv  = (const float*)d_in[6];  const float* bv  = (const float*)d_in[7];
    const float* Wqg = (const float*)d_in[8];  const float* bqg = (const float*)d_in[9];
    const float* Wkg = (const float*)d_in[10]; const float* bkg = (const float*)d_in[11];
    const float* Wvg = (const float*)d_in[12]; const float* bvg = (const float*)d_in[13];
    const float* Wo  = (const float*)d_in[14]; const float* bo  = (const float*)d_in[15];
    float* out = (float*)d_out;

    bf16 *xh, *xl, *qh, *ql, *kh, *kl, *vh, *vl, *ahp, *alp, *wh, *wl;
    float *kgp, *vgp, *qgp, *partp;
    cudaGetSymbolAddress((void**)&xh,  g_xh);  cudaGetSymbolAddress((void**)&xl,  g_xl);
    cudaGetSymbolAddress((void**)&qh,  g_qh);  cudaGetSymbolAddress((void**)&ql,  g_ql);
    cudaGetSymbolAddress((void**)&kh,  g_kh);  cudaGetSymbolAddress((void**)&kl,  g_kl);
    cudaGetSymbolAddress((void**)&vh,  g_vh);  cudaGetSymbolAddress((void**)&vl,  g_vl);
    cudaGetSymbolAddress((void**)&ahp, g_ah);  cudaGetSymbolAddress((void**)&alp, g_al);
    cudaGetSymbolAddress((void**)&wh,  g_wh);  cudaGetSymbolAddress((void**)&wl,  g_wl);
    cudaGetSymbolAddress((void**)&kgp, g_kg);
    cudaGetSymbolAddress((void**)&vgp, g_vg);
    cudaGetSymbolAddress((void**)&qgp, g_qg);
    cudaGetSymbolAddress((void**)&partp, g_part);

    cudaFuncSetAttribute(gemm4_kernel,
        cudaFuncAttributeMaxDynamicSharedMemorySize, G4_SMEM);
    cudaFuncSetAttribute(qg2_kernel,
        cudaFuncAttributeMaxDynamicSharedMemorySize, QG_SMEM);
    cudaFuncSetAttribute(band2_kernel,
        cudaFuncAttributeMaxDynamicSharedMemorySize, BA2_SMEM);
    cudaFuncSetAttribute(gattn_partial_kernel,
        cudaFuncAttributeMaxDynamicSharedMemorySize, GA_SMEM);

    const float scaling = 0.125f;   // D^-0.5
    const long WSZ = (long)E_*E_;

    // ---- one-time conversions (batched, 4x ILP)
    conv_query_kernel<<<M_*E_/4/1024, 256>>>(query, xh, xl);
    {
        ConvBatch cb;
        const float* srcs[7] = {Wq, Wk, Wv, Wkg, Wvg, Wo, Wqg};
        for (int i = 0; i < 7; i++) {
            cb.src[i] = srcs[i];
            cb.oh[i]  = wh + (long)i*WSZ;
            cb.ol[i]  = wl + (long)i*WSZ;
        }
        conv_batch_kernel<<<dim3(E_*E_/4/1024, 7), 256>>>(cb);
    }
    cudaMemsetAsync(qgp, 0, (size_t)B_*G_*E_*sizeof(float));

    // ---- batched projections: q,k,v (split out) + kg,vg (fp32 out)
    {
        G3Batch bt;
        const float* biases[5] = {bq, bk, bv, bkg, bvg};
        bf16* chs[5] = {qh, kh, vh, nullptr, nullptr};
        bf16* cls[5] = {ql, kl, vl, nullptr, nullptr};
        float* cfs[5] = {nullptr, nullptr, nullptr, kgp, vgp};
        for (int i = 0; i < 5; i++) {
            bt.Ah[i] = xh; bt.Al[i] = xl;
            bt.Bh[i] = wh + (long)i*WSZ; bt.Bl[i] = wl + (long)i*WSZ;
            bt.bias[i] = biases[i];
            bt.alpha[i] = (i == 0) ? scaling : 1.f;
            bt.Cf[i] = cfs[i]; bt.Ch[i] = chs[i]; bt.Cl[i] = cls[i];
            bt.omode[i] = (i < 3) ? 2 : 0;
        }
        gemm4_kernel<<<dim3(E_/128, M_/128, 5), 256, G4_SMEM>>>(bt);
    }

    // qg projection: pre-split inputs, split-K
    qg2_kernel<<<dim3(E_/128, 8), 256, QG_SMEM>>>(xh, xl, wh+6*WSZ, wl+6*WSZ,
                                                  bqg, qgp, scaling);

    // band + global-key attention (3-stage, 1 CTA/SM)
    band2_kernel<<<dim3(T_/128, H_, B_), 256, BA2_SMEM>>>(qh, ql, kh, kl, vh, vl, ahp, alp);

    // global tokens overwrite first G rows (split out)
    gattn_partial_kernel<<<dim3(NSPLIT, H_, B_), 128, GA_SMEM>>>(qgp, kgp, vgp, partp);
    gattn_combine_kernel<<<dim3(H_, B_), 64>>>(partp, ahp, alp);

    // output projection: attn(split) @ Wo^T + bo -> fp32 [T,B,E]
    {
        G3Batch bt;
        for (int i = 0; i < 5; i++) {
            bt.Ah[i] = ahp; bt.Al[i] = alp;
            bt.Bh[i] = wh + 5*WSZ; bt.Bl[i] = wl + 5*WSZ;
            bt.bias[i] = bo; bt.alpha[i] = 1.f;
            bt.Cf[i] = out; bt.Ch[i] = nullptr; bt.Cl[i] = nullptr;
            bt.omode[i] = 1;
        }
        gemm4_kernel<<<dim3(E_/128, M_/128, 1), 256, G4_SMEM>>>(bt);
    }
}